// round 14
// baseline (speedup 1.0000x reference)
#include <cuda_runtime.h>
#include <cuda_fp16.h>

#define BN_EPS 1e-5f

// ---------------- device scratch (static, allocation-free) ----------------
__device__ float g_wT[640 * 64];            // transposed 1x1 weights [c][o]
__device__ float g_s1x1[64], g_t1x1[64];    // bn_1x1 affine
__device__ float g_c1c[4];                  // c1: s2,t2,s1,t1
__device__ float g_k2[9], g_k1[9];          // c1 3x3 kernels
__device__ float g_alpha[16], g_beta[16];   // c1 proj+bnp folded
__device__ float g_w2t[144 * 16];           // c2 conv_uv weights [i*9+dd][o]
__device__ float g_s2c[16], g_t2c[16];      // c2 bn2 affine
__device__ float g_weff[144];               // c2 conv_hw collapsed weights
__device__ float g_fin[2];                  // final affine
__device__ float g_tsort[16];               // sorted relu breakpoints
__device__ int   g_rank[16];                // rank of each breakpoint
__device__ uint2 g_cabh[18 * 72];           // fp16 PWL table [k][s][opair]=(cA01,cB01)
__device__ float g_sctr[5 * 100 * 640];     // centered support
__device__ float g_qctr[75 * 100 * 640];    // centered query
__device__ float g_sf[5 * 100 * 64];        // normalized support feats
__device__ float g_qf[75 * 100 * 64];       // normalized query feats
__device__ float g_corr[375 * 10000];       // corr [b][ij][kl]
__device__ float g_y2[2 * 375 * 10000];     // c1 output per branch
__device__ __half g_Bh[2 * 60000000];       // conv_uv+relu output, fp16, per branch
__device__ float g_cca[375 * 10000];        // branch A output
__device__ float g_ccb[375 * 10000];        // branch B output (same index frame)

#define FMA2(acc, a, b) \
    asm("fma.rn.f32x2 %0, %1, %2, %0;" : "+l"(acc) : "l"(a), "l"(b))
#define ADD2(acc, a) \
    asm("add.rn.f32x2 %0, %0, %1;" : "+l"(acc) : "l"(a))
#define DUP2(out, f) \
    asm("mov.b64 %0, {%1, %1};" : "=l"(out) : "r"(__float_as_uint(f)))
#define UNPK2(lo, hi, in) \
    asm("mov.b64 {%0, %1}, %2;" : "=r"(lo), "=r"(hi) : "l"(in))
#define PACKF2(out, f2) \
    asm("mov.b64 %0, {%1, %2};" : "=l"(out) : "f"((f2).x), "f"((f2).y))

// ---------------- setup ----------------
__global__ void k_setup(const float* __restrict__ w1x1, const float* __restrict__ bn1x1,
                        const float* __restrict__ c1w2, const float* __restrict__ c1bn2,
                        const float* __restrict__ c1w1, const float* __restrict__ c1bn1,
                        const float* __restrict__ c1proj, const float* __restrict__ c1bnp,
                        const float* __restrict__ c2w2, const float* __restrict__ c2bn2,
                        const float* __restrict__ c2w1, const float* __restrict__ c2bn1,
                        const float* __restrict__ c2proj, const float* __restrict__ c2bnp) {
    int t = threadIdx.x;
    for (int e = t; e < 640 * 64; e += blockDim.x) {
        int o = e & 63, c = e >> 6;
        g_wT[e] = w1x1[o * 640 + c];
    }
    if (t < 64) {
        float s = bn1x1[t] * rsqrtf(bn1x1[3 * 64 + t] + BN_EPS);
        g_s1x1[t] = s;
        g_t1x1[t] = bn1x1[64 + t] - bn1x1[2 * 64 + t] * s;
    }
    if (t == 0) {
        float s2 = c1bn2[0] * rsqrtf(c1bn2[3] + BN_EPS);
        g_c1c[0] = s2; g_c1c[1] = c1bn2[1] - c1bn2[2] * s2;
        float s1 = c1bn1[0] * rsqrtf(c1bn1[3] + BN_EPS);
        g_c1c[2] = s1; g_c1c[3] = c1bn1[1] - c1bn1[2] * s1;
        float sp2 = c2bnp[0] * rsqrtf(c2bnp[3] + BN_EPS);
        float C = 0.f;
        for (int o = 0; o < 16; o++) {
            float s1c = c2bn1[o] * rsqrtf(c2bn1[3 * 16 + o] + BN_EPS);
            float t1c = c2bn1[16 + o] - c2bn1[2 * 16 + o] * s1c;
            C += c2proj[o] * t1c;
        }
        g_fin[0] = sp2;
        g_fin[1] = sp2 * C + c2bnp[1] - c2bnp[2] * sp2;
    }
    if (t < 9) { g_k2[t] = c1w2[t]; g_k1[t] = c1w1[t]; }
    if (t < 16) {
        float sp = c1bnp[t] * rsqrtf(c1bnp[3 * 16 + t] + BN_EPS);
        g_alpha[t] = sp * c1proj[t];
        g_beta[t] = c1bnp[16 + t] - c1bnp[2 * 16 + t] * sp;
        float s2c = c2bn2[t] * rsqrtf(c2bn2[3 * 16 + t] + BN_EPS);
        g_s2c[t] = s2c;
        g_t2c[t] = c2bn2[16 + t] - c2bn2[2 * 16 + t] * s2c;
    }
    for (int e = t; e < 2304; e += blockDim.x) {
        int m = e >> 4, o = e & 15;
        int i = m / 9, dd = m % 9;
        g_w2t[e] = c2w2[(o * 16 + i) * 9 + dd];
    }
    for (int e = t; e < 144; e += blockDim.x) {
        int i = e / 9, dd = e % 9;
        float acc = 0.f;
        for (int o = 0; o < 16; o++) {
            float s1c = c2bn1[o] * rsqrtf(c2bn1[3 * 16 + o] + BN_EPS);
            acc += c2proj[o] * s1c * c2w1[(o * 16 + i) * 9 + dd];
        }
        g_weff[e] = acc;
    }
    __syncthreads();
    if (t == 0) {
        float ts[16];
        for (int i = 0; i < 16; i++) {
            float a = g_alpha[i];
            ts[i] = (a != 0.f) ? (-g_beta[i] / a) : 3e38f;
        }
        for (int i = 0; i < 16; i++) {
            int r = 0;
            for (int j = 0; j < 16; j++)
                r += (ts[j] < ts[i]) || (ts[j] == ts[i] && j < i);
            g_rank[i] = r;
            g_tsort[r] = ts[i];
        }
    }
    __syncthreads();
    for (int e = t; e < 18 * 72; e += blockDim.x) {
        int k = e / 72, rem = e % 72, s = rem / 8, op = rem % 8;
        float cA0 = 0.f, cA1 = 0.f, cB0 = 0.f, cB1 = 0.f;
        if (k < 17) {
            for (int i = 0; i < 16; i++) {
                float a = g_alpha[i], bet = g_beta[i];
                bool act;
                if (a > 0.f)      act = (g_rank[i] < k);
                else if (a < 0.f) act = (g_rank[i] >= k);
                else              act = (bet > 0.f);
                if (act) {
                    float w0 = g_w2t[(i * 9 + s) * 16 + op * 2];
                    float w1 = g_w2t[(i * 9 + s) * 16 + op * 2 + 1];
                    cA0 += w0 * a; cA1 += w1 * a;
                    cB0 += w0 * bet; cB1 += w1 * bet;
                }
            }
        }
        __half2 ha = __floats2half2_rn(cA0, cA1);
        __half2 hb = __floats2half2_rn(cB0, cB1);
        g_cabh[e] = make_uint2(*reinterpret_cast<unsigned int*>(&ha),
                               *reinterpret_cast<unsigned int*>(&hb));
    }
}

// ---------------- feature: warp-per-pixel, coalesced load, FFMA2 dot ------
__global__ void __launch_bounds__(512) k_feat(const float* __restrict__ spt,
                                              const float* __restrict__ qry) {
    __shared__ float xs[16][645];
    int t = threadIdx.x;
    int pl = t >> 5, tt = t & 31;
    int Pbase = blockIdx.x * 16;
    for (int e = t; e < 16 * 640; e += 512) {
        int p_l = e & 15, c = e >> 4;
        int P = Pbase + p_l;
        const float* src;
        if (P < 500) src = spt + (P / 100) * 64000 + (P % 100);
        else { int Pq = P - 500; src = qry + (Pq / 100) * 64000 + (Pq % 100); }
        xs[p_l][c] = src[c * 100];
    }
    __syncthreads();
    int P = Pbase + pl;
    float* ctr;
    float* fout;
    if (P < 500) { ctr = g_sctr + P * 640; fout = g_sf + P * 64; }
    else { int Pq = P - 500; ctr = g_qctr + Pq * 640; fout = g_qf + Pq * 64; }
    float part = 0.f;
    for (int c = tt; c < 640; c += 32) part += xs[pl][c];
#pragma unroll
    for (int off = 16; off; off >>= 1) part += __shfl_xor_sync(0xffffffffu, part, off);
    float mean = part * (1.f / 640.f);
    for (int c = tt; c < 640; c += 32) {
        float v = xs[pl][c] - mean;
        xs[pl][c] = v;
        ctr[c] = v;
    }
    __syncwarp();
    const unsigned long long* wq = (const unsigned long long*)g_wT;
    unsigned long long acc2 = 0ull;
#pragma unroll 4
    for (int c = 0; c < 640; c++) {
        unsigned long long w = wq[c * 32 + tt];
        unsigned long long xd;
        DUP2(xd, xs[pl][c]);
        FMA2(acc2, w, xd);
    }
    unsigned int lo, hi;
    UNPK2(lo, hi, acc2);
    int o0 = 2 * tt, o1 = 2 * tt + 1;
    float y0 = fmaxf(g_s1x1[o0] * __uint_as_float(lo) + g_t1x1[o0], 0.f);
    float y1 = fmaxf(g_s1x1[o1] * __uint_as_float(hi) + g_t1x1[o1], 0.f);
    float ss = y0 * y0 + y1 * y1;
#pragma unroll
    for (int off = 16; off; off >>= 1) ss += __shfl_xor_sync(0xffffffffu, ss, off);
    float den = fmaxf(sqrtf(ss), 1e-8f);
    fout[o0] = y0 / den;
    fout[o1] = y1 / den;
}

// ---------------- correlation (FFMA2) + merged qry_pool -------------------
__global__ void __launch_bounds__(512) k_corr(float* __restrict__ out) {
    int blk = blockIdx.x, t = threadIdx.x;
    if (blk >= 375) {
        int q = blk - 375;
        for (int c = t; c < 640; c += 512) {
            float acc = 0.f;
            for (int p = 0; p < 100; p++) acc += g_qctr[(q * 100 + p) * 640 + c];
            out[375 + q * 640 + c] = acc * 0.01f;
        }
        return;
    }
    __shared__ __align__(16) float sfs[100 * 64];
    int b = blk, q = b / 5, n = b % 5;
    for (int e = t; e < 6400; e += 512) sfs[e] = g_sf[n * 6400 + e];
    __syncthreads();
    if (t < 400) {
        int kl = t % 100, ijg = t / 100;
        ulonglong2 qv[16];
        const ulonglong2* qp = (const ulonglong2*)(g_qf + (q * 100 + kl) * 64);
#pragma unroll
        for (int c = 0; c < 16; c++) qv[c] = qp[c];
        float* dst = g_corr + b * 10000 + kl;
        for (int ij = ijg * 25; ij < ijg * 25 + 25; ij++) {
            const ulonglong2* sp = (const ulonglong2*)(sfs + ij * 64);
            unsigned long long acc2 = 0ull;
#pragma unroll
            for (int c = 0; c < 16; c++) {
                ulonglong2 s2 = sp[c];
                FMA2(acc2, s2.x, qv[c].x);
                FMA2(acc2, s2.y, qv[c].y);
            }
            unsigned int lo, hi;
            UNPK2(lo, hi, acc2);
            dst[ij * 100] = __uint_as_float(lo) + __uint_as_float(hi);
        }
    }
}

// ---------------- c1: strength-reduced convs (constant tap offsets) --------
__global__ void __launch_bounds__(256) k_c1() {
    __shared__ float xs[100 * 101];
    int bb = blockIdx.x;
    int br = bb >= 375;
    int b = br ? bb - 375 : bb;
    int t = threadIdx.x;
    const float* src = g_corr + b * 10000;
    for (int e = t; e < 10000; e += 256) {
        float v = src[e];
        int row = br ? (e % 100) : (e / 100);
        int col = br ? (e / 100) : (e % 100);
        xs[row * 101 + col] = v;
    }
    float s2 = g_c1c[0], t2 = g_c1c[1], s1 = g_c1c[2], t1 = g_c1c[3];
    float k2[9], k1[9];
#pragma unroll
    for (int i = 0; i < 9; i++) { k2[i] = g_k2[i]; k1[i] = g_k1[i]; }
    __syncthreads();
    int g = t / 100, hw = t % 100;
    float y1r[50];
    if (t < 200) {
        int uv0 = g * 50;
        const float* base = xs + uv0 * 101 + hw;
        int u = g * 5, v = 0;
#pragma unroll 1
        for (int i = 0; i < 50; i++) {
            float acc = 0.f;
#pragma unroll
            for (int du = -1; du <= 1; du++) {
                int uu = u + du;
                if (uu < 0 || uu > 9) continue;
#pragma unroll
                for (int dv = -1; dv <= 1; dv++) {
                    int vv = v + dv;
                    if (vv < 0 || vv > 9) continue;
                    acc += k2[(du + 1) * 3 + dv + 1] * base[du * 1010 + dv * 101];
                }
            }
            y1r[i] = fmaxf(s2 * acc + t2, 0.f);
            base += 101;
            if (++v == 10) { v = 0; u++; }
        }
    }
    __syncthreads();
    if (t < 200) {
        float* wb = xs + g * 50 * 101 + hw;
#pragma unroll 1
        for (int i = 0; i < 50; i++) { *wb = y1r[i]; wb += 101; }
    }
    __syncthreads();
    if (t < 200) {
        int h = hw / 10, w = hw % 10;
        float* dst = g_y2 + (br * 375 + b) * 10000 + g * 50 * 100 + hw;
        const float* base = xs + g * 50 * 101 + hw;
#pragma unroll 1
        for (int i = 0; i < 50; i++) {
            float acc = 0.f;
#pragma unroll
            for (int dh = -1; dh <= 1; dh++) {
                int hh = h + dh;
                if (hh < 0 || hh > 9) continue;
#pragma unroll
                for (int dw = -1; dw <= 1; dw++) {
                    int ww = w + dw;
                    if (ww < 0 || ww > 9) continue;
                    acc += k1[(dh + 1) * 3 + dw + 1] * base[dh * 10 + dw];
                }
            }
            dst[i * 100] = s1 * acc + t1;
            base += 101;
        }
    }
}

// ---------------- c2a: conv_uv via fp16 PWL table (448 thr, o-quarter) ----
// Table k-stride 74 (even) so each o-quarter row is one aligned LDS.128.
__global__ void __launch_bounds__(448) k_c2a() {
    __shared__ __align__(16) uint2 cab[18 * 74];
    __shared__ __align__(16) float4 Ypad[144];
    __shared__ unsigned int Kw[144];
    __shared__ __align__(16) float4 ys[100];
    __shared__ float tso[16];
    __shared__ float2 stv[16];
    int b = blockIdx.y, hwc = blockIdx.x, br = blockIdx.z;
    int t = threadIdx.x;
    for (int e = t; e < 18 * 72; e += 448) {
        int k = e / 72, r = e % 72;
        cab[k * 74 + r] = g_cabh[e];
    }
    if (t < 100)
        ys[t] = *(const float4*)(g_y2 + (br * 375 + b) * 10000 + t * 100 + hwc * 4);
    if (t < 16) { stv[t] = make_float2(g_s2c[t], g_t2c[t]); tso[t] = g_tsort[t]; }
    __syncthreads();
    for (int e = t; e < 144; e += 448) {
        int r = e / 12, c = e % 12;
        int u = r - 1, v = c - 1;
        float4 y;
        unsigned int kw;
        if (u >= 0 && u < 10 && v >= 0 && v < 10) {
            y = ys[u * 10 + v];
            unsigned int k0 = 0, k1 = 0, k2 = 0, k3 = 0;
#pragma unroll
            for (int j = 0; j < 16; j++) {
                float tj = tso[j];
                k0 += (y.x > tj); k1 += (y.y > tj);
                k2 += (y.z > tj); k3 += (y.w > tj);
            }
            kw = k0 | (k1 << 8) | (k2 << 16) | (k3 << 24);
        } else {
            y = make_float4(0.f, 0.f, 0.f, 0.f);
            kw = 17u | (17u << 8) | (17u << 16) | (17u << 24);
        }
        Ypad[e] = y;
        Kw[e] = kw;
    }
    __syncthreads();
    if (t < 400) {
        int oq = t / 100, uv = t % 100;     // oq -> o-pairs {2oq, 2oq+1}
        int base = (uv / 10 + 1) * 12 + (uv % 10 + 1);
        unsigned long long acc[8];          // [op2][j]
#pragma unroll
        for (int k = 0; k < 8; k++) acc[k] = 0ull;
#pragma unroll
        for (int s = 0; s < 9; s++) {
            int q = base + (s / 3 - 1) * 12 + (s % 3 - 1);
            float4 y4 = Ypad[q];
            unsigned int kw = Kw[q];
            unsigned long long yd0, yd1, yd2, yd3;
            DUP2(yd0, y4.x); DUP2(yd1, y4.y); DUP2(yd2, y4.z); DUP2(yd3, y4.w);
            int kk0 = (int)(kw & 255u), kk1 = (int)((kw >> 8) & 255u);
            int kk2 = (int)((kw >> 16) & 255u), kk3 = (int)(kw >> 24);
            int off = s * 8 + oq * 2;
            uint4 c0 = *(const uint4*)(cab + kk0 * 74 + off);
            uint4 c1 = *(const uint4*)(cab + kk1 * 74 + off);
            uint4 c2 = *(const uint4*)(cab + kk2 * 74 + off);
            uint4 c3 = *(const uint4*)(cab + kk3 * 74 + off);
            // cN = {cA(op0), cB(op0), cA(op1), cB(op1)} as half2 each
            float2 f;
            unsigned long long A, Bv;
            f = __half22float2(*(__half2*)&c0.x); PACKF2(A, f);
            f = __half22float2(*(__half2*)&c0.y); PACKF2(Bv, f);
            FMA2(acc[0], A, yd0); ADD2(acc[0], Bv);
            f = __half22float2(*(__half2*)&c0.z); PACKF2(A, f);
            f = __half22float2(*(__half2*)&c0.w); PACKF2(Bv, f);
            FMA2(acc[4], A, yd0); ADD2(acc[4], Bv);
            f = __half22float2(*(__half2*)&c1.x); PACKF2(A, f);
            f = __half22float2(*(__half2*)&c1.y); PACKF2(Bv, f);
            FMA2(acc[1], A, yd1); ADD2(acc[1], Bv);
            f = __half22float2(*(__half2*)&c1.z); PACKF2(A, f);
            f = __half22float2(*(__half2*)&c1.w); PACKF2(Bv, f);
            FMA2(acc[5], A, yd1); ADD2(acc[5], Bv);
            f = __half22float2(*(__half2*)&c2.x); PACKF2(A, f);
            f = __half22float2(*(__half2*)&c2.y); PACKF2(Bv, f);
            FMA2(acc[2], A, yd2); ADD2(acc[2], Bv);
            f = __half22float2(*(__half2*)&c2.z); PACKF2(A, f);
            f = __half22float2(*(__half2*)&c2.w); PACKF2(Bv, f);
            FMA2(acc[6], A, yd2); ADD2(acc[6], Bv);
            f = __half22float2(*(__half2*)&c3.x); PACKF2(A, f);
            f = __half22float2(*(__half2*)&c3.y); PACKF2(Bv, f);
            FMA2(acc[3], A, yd3); ADD2(acc[3], Bv);
            f = __half22float2(*(__half2*)&c3.z); PACKF2(A, f);
            f = __half22float2(*(__half2*)&c3.w); PACKF2(Bv, f);
            FMA2(acc[7], A, yd3); ADD2(acc[7], Bv);
        }
        __half* Bout = g_Bh + br * 60000000;
#pragma unroll
        for (int op2 = 0; op2 < 2; op2++) {
            int opg = oq * 2 + op2;
            int o0 = 2 * opg, o1 = 2 * opg + 1;
            float4 vlo, vhi;
            unsigned int l0, h0, l1, h1, l2, h2, l3, h3;
            UNPK2(l0, h0, acc[op2 * 4 + 0]);
            UNPK2(l1, h1, acc[op2 * 4 + 1]);
            UNPK2(l2, h2, acc[op2 * 4 + 2]);
            UNPK2(l3, h3, acc[op2 * 4 + 3]);
            vlo.x = __uint_as_float(l0); vhi.x = __uint_as_float(h0);
            vlo.y = __uint_as_float(l1); vhi.y = __uint_as_float(h1);
            vlo.z = __uint_as_float(l2); vhi.z = __uint_as_float(h2);
            vlo.w = __uint_as_float(l3); vhi.w = __uint_as_float(h3);
            float2 s0 = stv[o0], s1 = stv[o1];
            __half2 p00 = __floats2half2_rn(fmaxf(s0.x * vlo.x + s0.y, 0.f),
                                            fmaxf(s0.x * vlo.y + s0.y, 0.f));
            __half2 p01 = __floats2half2_rn(fmaxf(s0.x * vlo.z + s0.y, 0.f),
                                            fmaxf(s0.x * vlo.w + s0.y, 0.f));
            __half2 p10 = __floats2half2_rn(fmaxf(s1.x * vhi.x + s1.y, 0.f),
                                            fmaxf(s1.x * vhi.y + s1.y, 0.f));
            __half2 p11 = __floats2half2_rn(fmaxf(s1.x * vhi.z + s1.y, 0.f),
                                            fmaxf(s1.x * vhi.w + s1.y, 0.f));
            *(__half2*)(Bout + (((b * 16 + o0) * 25 + hwc) * 100 + uv) * 4)     = p00;
            *(__half2*)(Bout + (((b * 16 + o0) * 25 + hwc) * 100 + uv) * 4 + 2) = p01;
            *(__half2*)(Bout + (((b * 16 + o1) * 25 + hwc) * 100 + uv) * 4)     = p10;
            *(__half2*)(Bout + (((b * 16 + o1) * 25 + hwc) * 100 + uv) * 4 + 2) = p11;
        }
    }
}

// ---------------- c2b: row-restructured 16->1 conv over (h,w) -------------
__global__ void __launch_bounds__(128) k_c2b() {
    __shared__ __half Bs[16 * 10 * 120];
    __shared__ float weffs[144];
    __shared__ float fin2[2];
    int b = blockIdx.y, uc = blockIdx.x, br = blockIdx.z;
    int t = threadIdx.x;
    for (int e = t; e < 144; e += 128) weffs[e] = g_weff[e];
    if (t < 2) fin2[t] = g_fin[t];
    for (int e = t; e < 3200; e += 128) {
        int i = e / 200, rem = e % 200;
        int uvl = rem / 20, rem2 = rem % 20;
        int h = rem2 / 2, side = rem2 % 2;
        Bs[(i * 10 + uvl) * 120 + h * 12 + side * 11] = __float2half(0.f);
    }
    const __half* Bin = g_Bh + br * 60000000;
    for (int e = t; e < 4000; e += 128) {
        int i = e / 250, r1 = e % 250;
        int hw4 = r1 / 10, uvl = r1 % 10;
        uint2 v = *(const uint2*)(Bin + (((b * 16 + i) * 25 + hw4) * 100 + uc * 10 + uvl) * 4);
        __half2 h01 = *reinterpret_cast<__half2*>(&v.x);
        __half2 h23 = *reinterpret_cast<__half2*>(&v.y);
        int hwb = hw4 * 4;
        int base = (i * 10 + uvl) * 120;
        Bs[base + ((hwb + 0) / 10) * 12 + (hwb + 0) % 10 + 1] = __low2half(h01);
        Bs[base + ((hwb + 1) / 10) * 12 + (hwb + 1) % 10 + 1] = __high2half(h01);
        Bs[base + ((hwb + 2) / 10) * 12 + (hwb + 2) % 10 + 1] = __low2half(h23);
        Bs[base + ((hwb + 3) / 10) * 12 + (hwb + 3) % 10 + 1] = __high2half(h23);
    }
    __syncthreads();
    if (t < 100) {
        int uvl = t / 10, h = t % 10;
        float acc[10];
#pragma unroll
        for (int w = 0; w < 10; w++) acc[w] = 0.f;
#pragma unroll 1
        for (int i = 0; i < 16; i++) {
            const float* wp = weffs + i * 9;
            int base_i = (i * 10 + uvl) * 120;
#pragma unroll
            for (int dh = 0; dh < 3; dh++) {
                int hh = h + dh - 1;
                if (hh < 0 || hh > 9) continue;
                const __half2* rp = (const __half2*)(Bs + base_i + hh * 12);
                float r[12];
#pragma unroll
                for (int m = 0; m < 6; m++) {
                    float2 f = __half22float2(rp[m]);
                    r[2 * m] = f.x; r[2 * m + 1] = f.y;
                }
                float k0 = wp[dh * 3 + 0], k1 = wp[dh * 3 + 1], k2 = wp[dh * 3 + 2];
#pragma unroll
                for (int w = 0; w < 10; w++)
                    acc[w] += k0 * r[w] + k1 * r[w + 1] + k2 * r[w + 2];
            }
        }
        int uv = uc * 10 + uvl;
#pragma unroll
        for (int w = 0; w < 10; w++) {
            float outv = fin2[0] * acc[w] + fin2[1];
            int hw = h * 10 + w;
            if (br) {
                g_ccb[b * 10000 + hw * 100 + uv] = outv;
            } else {
                g_cca[b * 10000 + uv * 100 + hw] = outv;
            }
        }
    }
}

// ---------------- attention + final, fused (no max pass: args in [-2,2]) --
__global__ void __launch_bounds__(256) k_attnfin(float* __restrict__ out) {
    __shared__ float Ms[100 * 101];
    __shared__ float cm[100], cs[100], ci[100];
    __shared__ float rm[100], rv[100], ri[100];
    __shared__ float as_[100], aq_[100];
    __shared__ float red[3][8];
    int b = blockIdx.x, q = b / 5, n = b % 5, t = threadIdx.x;
    const float* srca = g_cca + b * 10000;
    const float* srcb = g_ccb + b * 10000;
    for (int e = t; e < 10000; e += 256)
        Ms[(e / 100) * 101 + (e % 100)] = srca[e] + srcb[e];
    __syncthreads();
    if (t < 100) {
        float m = 0.f;
        for (int ij = 0; ij < 100; ij++) m += Ms[ij * 101 + t];
        m *= 0.01f;
        float vv = 0.f;
        for (int ij = 0; ij < 100; ij++) { float d = Ms[ij * 101 + t] - m; vv += d * d; }
        float r = rsqrtf(vv * (1.f / 99.f) + 1e-5f) * 0.2f;
        float se = 0.f;
        for (int ij = 0; ij < 100; ij++) se += __expf((Ms[ij * 101 + t] - m) * r);
        cm[t] = m; cs[t] = r; ci[t] = 1.f / se;
    } else if (t >= 128 && t < 228) {
        int rr = t - 128;
        float m2 = 0.f;
        for (int kl = 0; kl < 100; kl++) m2 += Ms[rr * 101 + kl];
        m2 *= 0.01f;
        float vv2 = 0.f;
        for (int kl = 0; kl < 100; kl++) { float d = Ms[rr * 101 + kl] - m2; vv2 += d * d; }
        float r2 = rsqrtf(vv2 * (1.f / 99.f) + 1e-5f) * 0.2f;
        float se2 = 0.f;
        for (int kl = 0; kl < 100; kl++) se2 += __expf((Ms[rr * 101 + kl] - m2) * r2);
        rm[rr] = m2; rv[rr] = r2; ri[rr] = 1.f / se2;
    }
    __syncthreads();
    if (t < 100) {
        float a = 0.f;
        for (int kl = 0; kl < 100; kl++)
            a += __expf((Ms[t * 101 + kl] - cm[kl]) * cs[kl]) * ci[kl];
        as_[t] = a;
    } else if (t >= 128 && t < 228) {
        int rr = t - 128;
        float a2 = 0.f;
        for (int ij = 0; ij < 100; ij++)
            a2 += __expf((Ms[ij * 101 + rr] - rm[ij]) * rv[ij]) * ri[ij];
        aq_[rr] = a2;
    }
    __syncthreads();
    float dot = 0.f, ns = 0.f, nq = 0.f;
    for (int e = t; e < 320; e += 256) {
        int c = e * 2;
        const unsigned long long* sp = (const unsigned long long*)(g_sctr + n * 64000 + c);
        const unsigned long long* qp = (const unsigned long long*)(g_qctr + q * 64000 + c);
        unsigned long long sacc = 0ull, qacc = 0ull;
        for (int p = 0; p < 100; p++) {
            unsigned long long sa, qa;
            DUP2(sa, as_[p]);
            DUP2(qa, aq_[p]);
            FMA2(sacc, sa, sp[p * 320]);
            FMA2(qacc, qa, qp[p * 320]);
        }
        unsigned int sl, sh, ql, qh;
        UNPK2(sl, sh, sacc);
        UNPK2(ql, qh, qacc);
        float s0 = __uint_as_float(sl) * 0.01f, s1 = __uint_as_float(sh) * 0.01f;
        float q0 = __uint_as_float(ql) * 0.01f, q1 = __uint_as_float(qh) * 0.01f;
        dot += s0 * q0 + s1 * q1;
        ns  += s0 * s0 + s1 * s1;
        nq  += q0 * q0 + q1 * q1;
    }
#pragma unroll
    for (int off = 16; off; off >>= 1) {
        dot += __shfl_xor_sync(0xffffffffu, dot, off);
        ns  += __shfl_xor_sync(0xffffffffu, ns, off);
        nq  += __shfl_xor_sync(0xffffffffu, nq, off);
    }
    int wid = t >> 5;
    if ((t & 31) == 0) { red[0][wid] = dot; red[1][wid] = ns; red[2][wid] = nq; }
    __syncthreads();
    if (t == 0) {
        float D = 0.f, NS = 0.f, NQ = 0.f;
#pragma unroll
        for (int wdx = 0; wdx < 8; wdx++) {
            D += red[0][wdx]; NS += red[1][wdx]; NQ += red[2][wdx];
        }
        float den = fmaxf(sqrtf(NS), 1e-8f) * fmaxf(sqrtf(NQ), 1e-8f);
        out[q * 5 + n] = (D / den) * 5.0f;
    }
}

extern "C" void kernel_launch(void* const* d_in, const int* in_sizes, int n_in,
                              void* d_out, int out_size) {
    const float* spt    = (const float*)d_in[0];
    const float* qry    = (const float*)d_in[1];
    const float* w1x1   = (const float*)d_in[2];
    const float* bn1x1  = (const float*)d_in[3];
    const float* c1w2   = (const float*)d_in[4];
    const float* c1bn2  = (const float*)d_in[5];
    const float* c1w1   = (const float*)d_in[6];
    const float* c1bn1  = (const float*)d_in[7];
    const float* c1proj = (const float*)d_in[8];
    const float* c1bnp  = (const float*)d_in[9];
    const float* c2w2   = (const float*)d_in[10];
    const float* c2bn2  = (const float*)d_in[11];
    const float* c2w1   = (const float*)d_in[12];
    const float* c2bn1  = (const float*)d_in[13];
    const float* c2proj = (const float*)d_in[14];
    const float* c2bnp  = (const float*)d_in[15];
    float* out = (float*)d_out;
    (void)in_sizes; (void)n_in; (void)out_size;

    k_setup<<<1, 256>>>(w1x1, bn1x1, c1w2, c1bn2, c1w1, c1bn1, c1proj, c1bnp,
                        c2w2, c2bn2, c2w1, c2bn1, c2proj, c2bnp);
    k_feat<<<500, 512>>>(spt, qry);
    k_corr<<<450, 512>>>(out);
    k_c1<<<750, 256>>>();
    k_c2a<<<dim3(25, 375, 2), 448>>>();
    k_c2b<<<dim3(10, 375, 2), 128>>>();
    k_attnfin<<<375, 256>>>(out);
}

// round 15
// speedup vs baseline: 1.0428x; 1.0428x over previous
#include <cuda_runtime.h>
#include <cuda_fp16.h>

#define BN_EPS 1e-5f

// ---------------- device scratch (static, allocation-free) ----------------
__device__ float g_wT[640 * 64];            // transposed 1x1 weights [c][o]
__device__ float g_s1x1[64], g_t1x1[64];    // bn_1x1 affine
__device__ float g_c1c[4];                  // c1: s2,t2,s1,t1
__device__ float g_k2[9], g_k1[9];          // c1 3x3 kernels
__device__ float g_alpha[16], g_beta[16];   // c1 proj+bnp folded
__device__ float g_w2t[144 * 16];           // c2 conv_uv weights [i*9+dd][o]
__device__ float g_s2c[16], g_t2c[16];      // c2 bn2 affine
__device__ float g_weff[144];               // c2 conv_hw collapsed weights
__device__ float g_fin[2];                  // final affine
__device__ float g_tsort[16];               // sorted relu breakpoints
__device__ int   g_rank[16];                // rank of each breakpoint
__device__ uint2 g_cabh[18 * 72];           // fp16 PWL table [k][s][opair]=(cA01,cB01)
__device__ float g_sctr[5 * 100 * 640];     // centered support
__device__ float g_qctr[75 * 100 * 640];    // centered query
__device__ float g_sf[5 * 100 * 64];        // normalized support feats
__device__ float g_qf[75 * 100 * 64];       // normalized query feats
__device__ float g_corr[375 * 10000];       // corr [b][ij][kl]
__device__ float g_y2[2 * 375 * 10000];     // c1 output per branch
__device__ __half g_Bh[2 * 60000000];       // conv_uv+relu output, fp16, per branch
__device__ float g_cca[375 * 10000];        // branch A output
__device__ float g_ccb[375 * 10000];        // branch B output (same index frame)

#define FMA2(acc, a, b) \
    asm("fma.rn.f32x2 %0, %1, %2, %0;" : "+l"(acc) : "l"(a), "l"(b))
#define ADD2(acc, a) \
    asm("add.rn.f32x2 %0, %0, %1;" : "+l"(acc) : "l"(a))
#define DUP2(out, f) \
    asm("mov.b64 %0, {%1, %1};" : "=l"(out) : "r"(__float_as_uint(f)))
#define UNPK2(lo, hi, in) \
    asm("mov.b64 {%0, %1}, %2;" : "=r"(lo), "=r"(hi) : "l"(in))
#define PACKF2(out, f2) \
    asm("mov.b64 %0, {%1, %2};" : "=l"(out) : "f"((f2).x), "f"((f2).y))

// ---------------- setup ----------------
__global__ void k_setup(const float* __restrict__ w1x1, const float* __restrict__ bn1x1,
                        const float* __restrict__ c1w2, const float* __restrict__ c1bn2,
                        const float* __restrict__ c1w1, const float* __restrict__ c1bn1,
                        const float* __restrict__ c1proj, const float* __restrict__ c1bnp,
                        const float* __restrict__ c2w2, const float* __restrict__ c2bn2,
                        const float* __restrict__ c2w1, const float* __restrict__ c2bn1,
                        const float* __restrict__ c2proj, const float* __restrict__ c2bnp) {
    int t = threadIdx.x;
    for (int e = t; e < 640 * 64; e += blockDim.x) {
        int o = e & 63, c = e >> 6;
        g_wT[e] = w1x1[o * 640 + c];
    }
    if (t < 64) {
        float s = bn1x1[t] * rsqrtf(bn1x1[3 * 64 + t] + BN_EPS);
        g_s1x1[t] = s;
        g_t1x1[t] = bn1x1[64 + t] - bn1x1[2 * 64 + t] * s;
    }
    if (t == 0) {
        float s2 = c1bn2[0] * rsqrtf(c1bn2[3] + BN_EPS);
        g_c1c[0] = s2; g_c1c[1] = c1bn2[1] - c1bn2[2] * s2;
        float s1 = c1bn1[0] * rsqrtf(c1bn1[3] + BN_EPS);
        g_c1c[2] = s1; g_c1c[3] = c1bn1[1] - c1bn1[2] * s1;
        float sp2 = c2bnp[0] * rsqrtf(c2bnp[3] + BN_EPS);
        float C = 0.f;
        for (int o = 0; o < 16; o++) {
            float s1c = c2bn1[o] * rsqrtf(c2bn1[3 * 16 + o] + BN_EPS);
            float t1c = c2bn1[16 + o] - c2bn1[2 * 16 + o] * s1c;
            C += c2proj[o] * t1c;
        }
        g_fin[0] = sp2;
        g_fin[1] = sp2 * C + c2bnp[1] - c2bnp[2] * sp2;
    }
    if (t < 9) { g_k2[t] = c1w2[t]; g_k1[t] = c1w1[t]; }
    if (t < 16) {
        float sp = c1bnp[t] * rsqrtf(c1bnp[3 * 16 + t] + BN_EPS);
        g_alpha[t] = sp * c1proj[t];
        g_beta[t] = c1bnp[16 + t] - c1bnp[2 * 16 + t] * sp;
        float s2c = c2bn2[t] * rsqrtf(c2bn2[3 * 16 + t] + BN_EPS);
        g_s2c[t] = s2c;
        g_t2c[t] = c2bn2[16 + t] - c2bn2[2 * 16 + t] * s2c;
    }
    for (int e = t; e < 2304; e += blockDim.x) {
        int m = e >> 4, o = e & 15;
        int i = m / 9, dd = m % 9;
        g_w2t[e] = c2w2[(o * 16 + i) * 9 + dd];
    }
    for (int e = t; e < 144; e += blockDim.x) {
        int i = e / 9, dd = e % 9;
        float acc = 0.f;
        for (int o = 0; o < 16; o++) {
            float s1c = c2bn1[o] * rsqrtf(c2bn1[3 * 16 + o] + BN_EPS);
            acc += c2proj[o] * s1c * c2w1[(o * 16 + i) * 9 + dd];
        }
        g_weff[e] = acc;
    }
    __syncthreads();
    if (t == 0) {
        float ts[16];
        for (int i = 0; i < 16; i++) {
            float a = g_alpha[i];
            ts[i] = (a != 0.f) ? (-g_beta[i] / a) : 3e38f;
        }
        for (int i = 0; i < 16; i++) {
            int r = 0;
            for (int j = 0; j < 16; j++)
                r += (ts[j] < ts[i]) || (ts[j] == ts[i] && j < i);
            g_rank[i] = r;
            g_tsort[r] = ts[i];
        }
    }
    __syncthreads();
    for (int e = t; e < 18 * 72; e += blockDim.x) {
        int k = e / 72, rem = e % 72, s = rem / 8, op = rem % 8;
        float cA0 = 0.f, cA1 = 0.f, cB0 = 0.f, cB1 = 0.f;
        if (k < 17) {
            for (int i = 0; i < 16; i++) {
                float a = g_alpha[i], bet = g_beta[i];
                bool act;
                if (a > 0.f)      act = (g_rank[i] < k);
                else if (a < 0.f) act = (g_rank[i] >= k);
                else              act = (bet > 0.f);
                if (act) {
                    float w0 = g_w2t[(i * 9 + s) * 16 + op * 2];
                    float w1 = g_w2t[(i * 9 + s) * 16 + op * 2 + 1];
                    cA0 += w0 * a; cA1 += w1 * a;
                    cB0 += w0 * bet; cB1 += w1 * bet;
                }
            }
        }
        __half2 ha = __floats2half2_rn(cA0, cA1);
        __half2 hb = __floats2half2_rn(cB0, cB1);
        g_cabh[e] = make_uint2(*reinterpret_cast<unsigned int*>(&ha),
                               *reinterpret_cast<unsigned int*>(&hb));
    }
}

// ---------------- feature: warp-per-pixel, coalesced load, FFMA2 dot ------
__global__ void __launch_bounds__(512) k_feat(const float* __restrict__ spt,
                                              const float* __restrict__ qry) {
    __shared__ float xs[16][645];
    int t = threadIdx.x;
    int pl = t >> 5, tt = t & 31;
    int Pbase = blockIdx.x * 16;
    for (int e = t; e < 16 * 640; e += 512) {
        int p_l = e & 15, c = e >> 4;
        int P = Pbase + p_l;
        const float* src;
        if (P < 500) src = spt + (P / 100) * 64000 + (P % 100);
        else { int Pq = P - 500; src = qry + (Pq / 100) * 64000 + (Pq % 100); }
        xs[p_l][c] = src[c * 100];
    }
    __syncthreads();
    int P = Pbase + pl;
    float* ctr;
    float* fout;
    if (P < 500) { ctr = g_sctr + P * 640; fout = g_sf + P * 64; }
    else { int Pq = P - 500; ctr = g_qctr + Pq * 640; fout = g_qf + Pq * 64; }
    float part = 0.f;
    for (int c = tt; c < 640; c += 32) part += xs[pl][c];
#pragma unroll
    for (int off = 16; off; off >>= 1) part += __shfl_xor_sync(0xffffffffu, part, off);
    float mean = part * (1.f / 640.f);
    for (int c = tt; c < 640; c += 32) {
        float v = xs[pl][c] - mean;
        xs[pl][c] = v;
        ctr[c] = v;
    }
    __syncwarp();
    const unsigned long long* wq = (const unsigned long long*)g_wT;
    unsigned long long acc2 = 0ull;
#pragma unroll 4
    for (int c = 0; c < 640; c++) {
        unsigned long long w = wq[c * 32 + tt];
        unsigned long long xd;
        DUP2(xd, xs[pl][c]);
        FMA2(acc2, w, xd);
    }
    unsigned int lo, hi;
    UNPK2(lo, hi, acc2);
    int o0 = 2 * tt, o1 = 2 * tt + 1;
    float y0 = fmaxf(g_s1x1[o0] * __uint_as_float(lo) + g_t1x1[o0], 0.f);
    float y1 = fmaxf(g_s1x1[o1] * __uint_as_float(hi) + g_t1x1[o1], 0.f);
    float ss = y0 * y0 + y1 * y1;
#pragma unroll
    for (int off = 16; off; off >>= 1) ss += __shfl_xor_sync(0xffffffffu, ss, off);
    float den = fmaxf(sqrtf(ss), 1e-8f);
    fout[o0] = y0 / den;
    fout[o1] = y1 / den;
}

// ---------------- correlation (FFMA2) + merged qry_pool -------------------
__global__ void __launch_bounds__(512) k_corr(float* __restrict__ out) {
    int blk = blockIdx.x, t = threadIdx.x;
    if (blk >= 375) {
        int q = blk - 375;
        for (int c = t; c < 640; c += 512) {
            float acc = 0.f;
            for (int p = 0; p < 100; p++) acc += g_qctr[(q * 100 + p) * 640 + c];
            out[375 + q * 640 + c] = acc * 0.01f;
        }
        return;
    }
    __shared__ __align__(16) float sfs[100 * 64];
    int b = blk, q = b / 5, n = b % 5;
    for (int e = t; e < 6400; e += 512) sfs[e] = g_sf[n * 6400 + e];
    __syncthreads();
    if (t < 400) {
        int kl = t % 100, ijg = t / 100;
        ulonglong2 qv[16];
        const ulonglong2* qp = (const ulonglong2*)(g_qf + (q * 100 + kl) * 64);
#pragma unroll
        for (int c = 0; c < 16; c++) qv[c] = qp[c];
        float* dst = g_corr + b * 10000 + kl;
        for (int ij = ijg * 25; ij < ijg * 25 + 25; ij++) {
            const ulonglong2* sp = (const ulonglong2*)(sfs + ij * 64);
            unsigned long long acc2 = 0ull;
#pragma unroll
            for (int c = 0; c < 16; c++) {
                ulonglong2 s2 = sp[c];
                FMA2(acc2, s2.x, qv[c].x);
                FMA2(acc2, s2.y, qv[c].y);
            }
            unsigned int lo, hi;
            UNPK2(lo, hi, acc2);
            dst[ij * 100] = __uint_as_float(lo) + __uint_as_float(hi);
        }
    }
}

// ---------------- c1: strength-reduced convs (constant tap offsets) --------
__global__ void __launch_bounds__(256) k_c1() {
    __shared__ float xs[100 * 101];
    int bb = blockIdx.x;
    int br = bb >= 375;
    int b = br ? bb - 375 : bb;
    int t = threadIdx.x;
    const float* src = g_corr + b * 10000;
    for (int e = t; e < 10000; e += 256) {
        float v = src[e];
        int row = br ? (e % 100) : (e / 100);
        int col = br ? (e / 100) : (e % 100);
        xs[row * 101 + col] = v;
    }
    float s2 = g_c1c[0], t2 = g_c1c[1], s1 = g_c1c[2], t1 = g_c1c[3];
    float k2[9], k1[9];
#pragma unroll
    for (int i = 0; i < 9; i++) { k2[i] = g_k2[i]; k1[i] = g_k1[i]; }
    __syncthreads();
    int g = t / 100, hw = t % 100;
    float y1r[50];
    if (t < 200) {
        int uv0 = g * 50;
        const float* base = xs + uv0 * 101 + hw;
        int u = g * 5, v = 0;
#pragma unroll 1
        for (int i = 0; i < 50; i++) {
            float acc = 0.f;
#pragma unroll
            for (int du = -1; du <= 1; du++) {
                int uu = u + du;
                if (uu < 0 || uu > 9) continue;
#pragma unroll
                for (int dv = -1; dv <= 1; dv++) {
                    int vv = v + dv;
                    if (vv < 0 || vv > 9) continue;
                    acc += k2[(du + 1) * 3 + dv + 1] * base[du * 1010 + dv * 101];
                }
            }
            y1r[i] = fmaxf(s2 * acc + t2, 0.f);
            base += 101;
            if (++v == 10) { v = 0; u++; }
        }
    }
    __syncthreads();
    if (t < 200) {
        float* wb = xs + g * 50 * 101 + hw;
#pragma unroll 1
        for (int i = 0; i < 50; i++) { *wb = y1r[i]; wb += 101; }
    }
    __syncthreads();
    if (t < 200) {
        int h = hw / 10, w = hw % 10;
        float* dst = g_y2 + (br * 375 + b) * 10000 + g * 50 * 100 + hw;
        const float* base = xs + g * 50 * 101 + hw;
#pragma unroll 1
        for (int i = 0; i < 50; i++) {
            float acc = 0.f;
#pragma unroll
            for (int dh = -1; dh <= 1; dh++) {
                int hh = h + dh;
                if (hh < 0 || hh > 9) continue;
#pragma unroll
                for (int dw = -1; dw <= 1; dw++) {
                    int ww = w + dw;
                    if (ww < 0 || ww > 9) continue;
                    acc += k1[(dh + 1) * 3 + dw + 1] * base[dh * 10 + dw];
                }
            }
            dst[i * 100] = s1 * acc + t1;
            base += 101;
        }
    }
}

// ---------------- c2a: conv_uv via fp16 PWL table (round-13 proven) -------
__global__ void __launch_bounds__(224) k_c2a() {
    __shared__ __align__(16) uint2 cab[18 * 73];
    __shared__ __align__(16) float4 Ypad[144];
    __shared__ unsigned int Kw[144];
    __shared__ __align__(16) float4 ys[100];
    __shared__ float tso[16];
    __shared__ float2 stv[16];
    int b = blockIdx.y, hwc = blockIdx.x, br = blockIdx.z;
    int t = threadIdx.x;
    for (int e = t; e < 18 * 72; e += 224) {
        int k = e / 72, r = e % 72;
        cab[k * 73 + r] = g_cabh[e];
    }
    if (t < 100)
        ys[t] = *(const float4*)(g_y2 + (br * 375 + b) * 10000 + t * 100 + hwc * 4);
    if (t < 16) { stv[t] = make_float2(g_s2c[t], g_t2c[t]); tso[t] = g_tsort[t]; }
    __syncthreads();
    for (int e = t; e < 144; e += 224) {
        int r = e / 12, c = e % 12;
        int u = r - 1, v = c - 1;
        float4 y;
        unsigned int kw;
        if (u >= 0 && u < 10 && v >= 0 && v < 10) {
            y = ys[u * 10 + v];
            unsigned int k0 = 0, k1 = 0, k2 = 0, k3 = 0;
#pragma unroll
            for (int j = 0; j < 16; j++) {
                float tj = tso[j];
                k0 += (y.x > tj); k1 += (y.y > tj);
                k2 += (y.z > tj); k3 += (y.w > tj);
            }
            kw = k0 | (k1 << 8) | (k2 << 16) | (k3 << 24);
        } else {
            y = make_float4(0.f, 0.f, 0.f, 0.f);
            kw = 17u | (17u << 8) | (17u << 16) | (17u << 24);
        }
        Ypad[e] = y;
        Kw[e] = kw;
    }
    __syncthreads();
    if (t < 200) {
        int o8 = t / 100, uv = t % 100;
        int base = (uv / 10 + 1) * 12 + (uv % 10 + 1);
        unsigned long long acc[16];
#pragma unroll
        for (int k = 0; k < 16; k++) acc[k] = 0ull;
#pragma unroll
        for (int s = 0; s < 9; s++) {
            int q = base + (s / 3 - 1) * 12 + (s % 3 - 1);
            float4 y4 = Ypad[q];
            unsigned int kw = Kw[q];
            unsigned long long yd0, yd1, yd2, yd3;
            DUP2(yd0, y4.x); DUP2(yd1, y4.y); DUP2(yd2, y4.z); DUP2(yd3, y4.w);
            int kk0 = (int)(kw & 255u), kk1 = (int)((kw >> 8) & 255u);
            int kk2 = (int)((kw >> 16) & 255u), kk3 = (int)(kw >> 24);
            const uint2* r0 = cab + kk0 * 73 + s * 8 + o8 * 4;
            const uint2* r1 = cab + kk1 * 73 + s * 8 + o8 * 4;
            const uint2* r2 = cab + kk2 * 73 + s * 8 + o8 * 4;
            const uint2* r3 = cab + kk3 * 73 + s * 8 + o8 * 4;
#pragma unroll
            for (int op = 0; op < 4; op++) {
                uint2 c0 = r0[op], c1 = r1[op], c2 = r2[op], c3 = r3[op];
                float2 a0 = __half22float2(*reinterpret_cast<__half2*>(&c0.x));
                float2 b0 = __half22float2(*reinterpret_cast<__half2*>(&c0.y));
                float2 a1 = __half22float2(*reinterpret_cast<__half2*>(&c1.x));
                float2 b1 = __half22float2(*reinterpret_cast<__half2*>(&c1.y));
                float2 a2 = __half22float2(*reinterpret_cast<__half2*>(&c2.x));
                float2 b2 = __half22float2(*reinterpret_cast<__half2*>(&c2.y));
                float2 a3 = __half22float2(*reinterpret_cast<__half2*>(&c3.x));
                float2 b3 = __half22float2(*reinterpret_cast<__half2*>(&c3.y));
                unsigned long long A0, B0, A1, B1, A2, B2, A3, B3;
                PACKF2(A0, a0); PACKF2(B0, b0);
                PACKF2(A1, a1); PACKF2(B1, b1);
                PACKF2(A2, a2); PACKF2(B2, b2);
                PACKF2(A3, a3); PACKF2(B3, b3);
                FMA2(acc[op * 4 + 0], A0, yd0); ADD2(acc[op * 4 + 0], B0);
                FMA2(acc[op * 4 + 1], A1, yd1); ADD2(acc[op * 4 + 1], B1);
                FMA2(acc[op * 4 + 2], A2, yd2); ADD2(acc[op * 4 + 2], B2);
                FMA2(acc[op * 4 + 3], A3, yd3); ADD2(acc[op * 4 + 3], B3);
            }
        }
        __half* Bout = g_Bh + br * 60000000;
#pragma unroll
        for (int op = 0; op < 4; op++) {
            int opg = o8 * 4 + op;
            int o0 = 2 * opg, o1 = 2 * opg + 1;
            float4 vlo, vhi;
            unsigned int l0, h0, l1, h1, l2, h2, l3, h3;
            UNPK2(l0, h0, acc[op * 4 + 0]);
            UNPK2(l1, h1, acc[op * 4 + 1]);
            UNPK2(l2, h2, acc[op * 4 + 2]);
            UNPK2(l3, h3, acc[op * 4 + 3]);
            vlo.x = __uint_as_float(l0); vhi.x = __uint_as_float(h0);
            vlo.y = __uint_as_float(l1); vhi.y = __uint_as_float(h1);
            vlo.z = __uint_as_float(l2); vhi.z = __uint_as_float(h2);
            vlo.w = __uint_as_float(l3); vhi.w = __uint_as_float(h3);
            float2 s0 = stv[o0], s1 = stv[o1];
            __half2 p00 = __floats2half2_rn(fmaxf(s0.x * vlo.x + s0.y, 0.f),
                                            fmaxf(s0.x * vlo.y + s0.y, 0.f));
            __half2 p01 = __floats2half2_rn(fmaxf(s0.x * vlo.z + s0.y, 0.f),
                                            fmaxf(s0.x * vlo.w + s0.y, 0.f));
            __half2 p10 = __floats2half2_rn(fmaxf(s1.x * vhi.x + s1.y, 0.f),
                                            fmaxf(s1.x * vhi.y + s1.y, 0.f));
            __half2 p11 = __floats2half2_rn(fmaxf(s1.x * vhi.z + s1.y, 0.f),
                                            fmaxf(s1.x * vhi.w + s1.y, 0.f));
            *(__half2*)(Bout + (((b * 16 + o0) * 25 + hwc) * 100 + uv) * 4)     = p00;
            *(__half2*)(Bout + (((b * 16 + o0) * 25 + hwc) * 100 + uv) * 4 + 2) = p01;
            *(__half2*)(Bout + (((b * 16 + o1) * 25 + hwc) * 100 + uv) * 4)     = p10;
            *(__half2*)(Bout + (((b * 16 + o1) * 25 + hwc) * 100 + uv) * 4 + 2) = p11;
        }
    }
}

// ---------------- c2b: row-restructured 16->1 conv over (h,w) -------------
__global__ void __launch_bounds__(128) k_c2b() {
    __shared__ __half Bs[16 * 10 * 120];
    __shared__ float weffs[144];
    __shared__ float fin2[2];
    int b = blockIdx.y, uc = blockIdx.x, br = blockIdx.z;
    int t = threadIdx.x;
    for (int e = t; e < 144; e += 128) weffs[e] = g_weff[e];
    if (t < 2) fin2[t] = g_fin[t];
    for (int e = t; e < 3200; e += 128) {
        int i = e / 200, rem = e % 200;
        int uvl = rem / 20, rem2 = rem % 20;
        int h = rem2 / 2, side = rem2 % 2;
        Bs[(i * 10 + uvl) * 120 + h * 12 + side * 11] = __float2half(0.f);
    }
    const __half* Bin = g_Bh + br * 60000000;
    for (int e = t; e < 4000; e += 128) {
        int i = e / 250, r1 = e % 250;
        int hw4 = r1 / 10, uvl = r1 % 10;
        uint2 v = *(const uint2*)(Bin + (((b * 16 + i) * 25 + hw4) * 100 + uc * 10 + uvl) * 4);
        __half2 h01 = *reinterpret_cast<__half2*>(&v.x);
        __half2 h23 = *reinterpret_cast<__half2*>(&v.y);
        int hwb = hw4 * 4;
        int base = (i * 10 + uvl) * 120;
        Bs[base + ((hwb + 0) / 10) * 12 + (hwb + 0) % 10 + 1] = __low2half(h01);
        Bs[base + ((hwb + 1) / 10) * 12 + (hwb + 1) % 10 + 1] = __high2half(h01);
        Bs[base + ((hwb + 2) / 10) * 12 + (hwb + 2) % 10 + 1] = __low2half(h23);
        Bs[base + ((hwb + 3) / 10) * 12 + (hwb + 3) % 10 + 1] = __high2half(h23);
    }
    __syncthreads();
    if (t < 100) {
        int uvl = t / 10, h = t % 10;
        float acc[10];
#pragma unroll
        for (int w = 0; w < 10; w++) acc[w] = 0.f;
#pragma unroll 1
        for (int i = 0; i < 16; i++) {
            const float* wp = weffs + i * 9;
            int base_i = (i * 10 + uvl) * 120;
#pragma unroll
            for (int dh = 0; dh < 3; dh++) {
                int hh = h + dh - 1;
                if (hh < 0 || hh > 9) continue;
                const __half2* rp = (const __half2*)(Bs + base_i + hh * 12);
                float r[12];
#pragma unroll
                for (int m = 0; m < 6; m++) {
                    float2 f = __half22float2(rp[m]);
                    r[2 * m] = f.x; r[2 * m + 1] = f.y;
                }
                float k0 = wp[dh * 3 + 0], k1 = wp[dh * 3 + 1], k2 = wp[dh * 3 + 2];
#pragma unroll
                for (int w = 0; w < 10; w++)
                    acc[w] += k0 * r[w] + k1 * r[w + 1] + k2 * r[w + 2];
            }
        }
        int uv = uc * 10 + uvl;
#pragma unroll
        for (int w = 0; w < 10; w++) {
            float outv = fin2[0] * acc[w] + fin2[1];
            int hw = h * 10 + w;
            if (br) {
                g_ccb[b * 10000 + hw * 100 + uv] = outv;
            } else {
                g_cca[b * 10000 + uv * 100 + hw] = outv;
            }
        }
    }
}

// ---------------- attention + final, fused (no max pass: args in [-2,2]) --
__global__ void __launch_bounds__(256) k_attnfin(float* __restrict__ out) {
    __shared__ float Ms[100 * 101];
    __shared__ float cm[100], cs[100], ci[100];
    __shared__ float rm[100], rv[100], ri[100];
    __shared__ float as_[100], aq_[100];
    __shared__ float red[3][8];
    int b = blockIdx.x, q = b / 5, n = b % 5, t = threadIdx.x;
    const float* srca = g_cca + b * 10000;
    const float* srcb = g_ccb + b * 10000;
    for (int e = t; e < 10000; e += 256)
        Ms[(e / 100) * 101 + (e % 100)] = srca[e] + srcb[e];
    __syncthreads();
    if (t < 100) {
        float m = 0.f;
        for (int ij = 0; ij < 100; ij++) m += Ms[ij * 101 + t];
        m *= 0.01f;
        float vv = 0.f;
        for (int ij = 0; ij < 100; ij++) { float d = Ms[ij * 101 + t] - m; vv += d * d; }
        float r = rsqrtf(vv * (1.f / 99.f) + 1e-5f) * 0.2f;
        float se = 0.f;
        for (int ij = 0; ij < 100; ij++) se += __expf((Ms[ij * 101 + t] - m) * r);
        cm[t] = m; cs[t] = r; ci[t] = 1.f / se;
    } else if (t >= 128 && t < 228) {
        int rr = t - 128;
        float m2 = 0.f;
        for (int kl = 0; kl < 100; kl++) m2 += Ms[rr * 101 + kl];
        m2 *= 0.01f;
        float vv2 = 0.f;
        for (int kl = 0; kl < 100; kl++) { float d = Ms[rr * 101 + kl] - m2; vv2 += d * d; }
        float r2 = rsqrtf(vv2 * (1.f / 99.f) + 1e-5f) * 0.2f;
        float se2 = 0.f;
        for (int kl = 0; kl < 100; kl++) se2 += __expf((Ms[rr * 101 + kl] - m2) * r2);
        rm[rr] = m2; rv[rr] = r2; ri[rr] = 1.f / se2;
    }
    __syncthreads();
    if (t < 100) {
        float a = 0.f;
        for (int kl = 0; kl < 100; kl++)
            a += __expf((Ms[t * 101 + kl] - cm[kl]) * cs[kl]) * ci[kl];
        as_[t] = a;
    } else if (t >= 128 && t < 228) {
        int rr = t - 128;
        float a2 = 0.f;
        for (int ij = 0; ij < 100; ij++)
            a2 += __expf((Ms[ij * 101 + rr] - rm[ij]) * rv[ij]) * ri[ij];
        aq_[rr] = a2;
    }
    __syncthreads();
    float dot = 0.f, ns = 0.f, nq = 0.f;
    for (int e = t; e < 320; e += 256) {
        int c = e * 2;
        const unsigned long long* sp = (const unsigned long long*)(g_sctr + n * 64000 + c);
        const unsigned long long* qp = (const unsigned long long*)(g_qctr + q * 64000 + c);
        unsigned long long sacc = 0ull, qacc = 0ull;
        for (int p = 0; p < 100; p++) {
            unsigned long long sa, qa;
            DUP2(sa, as_[p]);
            DUP2(qa, aq_[p]);
            FMA2(sacc, sa, sp[p * 320]);
            FMA2(qacc, qa, qp[p * 320]);
        }
        unsigned int sl, sh, ql, qh;
        UNPK2(sl, sh, sacc);
        UNPK2(ql, qh, qacc);
        float s0 = __uint_as_float(sl) * 0.01f, s1 = __uint_as_float(sh) * 0.01f;
        float q0 = __uint_as_float(ql) * 0.01f, q1 = __uint_as_float(qh) * 0.01f;
        dot += s0 * q0 + s1 * q1;
        ns  += s0 * s0 + s1 * s1;
        nq  += q0 * q0 + q1 * q1;
    }
#pragma unroll
    for (int off = 16; off; off >>= 1) {
        dot += __shfl_xor_sync(0xffffffffu, dot, off);
        ns  += __shfl_xor_sync(0xffffffffu, ns, off);
        nq  += __shfl_xor_sync(0xffffffffu, nq, off);
    }
    int wid = t >> 5;
    if ((t & 31) == 0) { red[0][wid] = dot; red[1][wid] = ns; red[2][wid] = nq; }
    __syncthreads();
    if (t == 0) {
        float D = 0.f, NS = 0.f, NQ = 0.f;
#pragma unroll
        for (int wdx = 0; wdx < 8; wdx++) {
            D += red[0][wdx]; NS += red[1][wdx]; NQ += red[2][wdx];
        }
        float den = fmaxf(sqrtf(NS), 1e-8f) * fmaxf(sqrtf(NQ), 1e-8f);
        out[q * 5 + n] = (D / den) * 5.0f;
    }
}

extern "C" void kernel_launch(void* const* d_in, const int* in_sizes, int n_in,
                              void* d_out, int out_size) {
    const float* spt    = (const float*)d_in[0];
    const float* qry    = (const float*)d_in[1];
    const float* w1x1   = (const float*)d_in[2];
    const float* bn1x1  = (const float*)d_in[3];
    const float* c1w2   = (const float*)d_in[4];
    const float* c1bn2  = (const float*)d_in[5];
    const float* c1w1   = (const float*)d_in[6];
    const float* c1bn1  = (const float*)d_in[7];
    const float* c1proj = (const float*)d_in[8];
    const float* c1bnp  = (const float*)d_in[9];
    const float* c2w2   = (const float*)d_in[10];
    const float* c2bn2  = (const float*)d_in[11];
    const float* c2w1   = (const float*)d_in[12];
    const float* c2bn1  = (const float*)d_in[13];
    const float* c2proj = (const float*)d_in[14];
    const float* c2bnp  = (const float*)d_in[15];
    float* out = (float*)d_out;
    (void)in_sizes; (void)n_in; (void)out_size;

    k_setup<<<1, 256>>>(w1x1, bn1x1, c1w2, c1bn2, c1w1, c1bn1, c1proj, c1bnp,
                        c2w2, c2bn2, c2w1, c2bn1, c2proj, c2bnp);
    k_feat<<<500, 512>>>(spt, qry);
    k_corr<<<450, 512>>>(out);
    k_c1<<<750, 256>>>();
    k_c2a<<<dim3(25, 375, 2), 224>>>();
    k_c2b<<<dim3(10, 375, 2), 128>>>();
    k_attnfin<<<375, 256>>>(out);
}